// round 5
// baseline (speedup 1.0000x reference)
#include <cuda_runtime.h>
#include <cuda_bf16.h>
#include <cstdint>

// C[b] = A[b](1024x64) @ B[b](64x1024), fp32, b in [0,24).
// Round 5: prepass splits A/B into bf16 hi/lo scratch in GEMM-ready swizzled
// tile layout (B transposed). GEMM: cp.async tiles, mma.sync bf16 3-term
// split, per-CTA loop over 4 n-tiles with double-buffered B.

#define M_DIM 1024
#define N_DIM 1024
#define K_DIM 64
#define BATCH 24
#define THREADS 256
#define NT_PER_CTA 4

#define TILE_BYTES 16384            // 128 rows x 64 bf16 (swizzled)
#define SW128(o) ((o) ^ (((o) >> 3) & 0x70))

// ---- scratch: pre-split bf16 tensors, tile-blocked + SW128-swizzled ----
__device__ __align__(16) __nv_bfloat16 gA0[BATCH * M_DIM * K_DIM];
__device__ __align__(16) __nv_bfloat16 gA1[BATCH * M_DIM * K_DIM];
__device__ __align__(16) __nv_bfloat16 gB0[BATCH * N_DIM * K_DIM];
__device__ __align__(16) __nv_bfloat16 gB1[BATCH * N_DIM * K_DIM];

// ---- smem layout (GEMM) ----
#define SMEM_A0 0
#define SMEM_A1 16384
#define SMEM_BS(s) (32768 + (s) * 32768)   // stage s: B0 at +0, B1 at +16384
#define SMEM_TOTAL 98304

// ---------------- helpers ----------------
__device__ __forceinline__ uint32_t smem_u32(const void* p) {
    uint32_t a;
    asm("{ .reg .u64 t; cvta.to.shared.u64 t, %1; cvt.u32.u64 %0, t; }"
        : "=r"(a) : "l"(p));
    return a;
}

__device__ __forceinline__ void cp16(uint32_t dst, const void* src) {
    asm volatile("cp.async.cg.shared.global [%0], [%1], 16;"
                 :: "r"(dst), "l"(src));
}
#define CP_COMMIT() asm volatile("cp.async.commit_group;" ::: "memory")

__device__ __forceinline__ void ldsm_x4(uint32_t* r, uint32_t addr) {
    asm volatile("ldmatrix.sync.aligned.m8n8.x4.shared.b16 {%0,%1,%2,%3}, [%4];"
                 : "=r"(r[0]), "=r"(r[1]), "=r"(r[2]), "=r"(r[3])
                 : "r"(addr));
}

__device__ __forceinline__ void mma_bf16(float* c, const uint32_t* a,
                                         uint32_t b0, uint32_t b1) {
    asm volatile(
        "mma.sync.aligned.m16n8k16.row.col.f32.bf16.bf16.f32 "
        "{%0,%1,%2,%3}, {%4,%5,%6,%7}, {%8,%9}, {%0,%1,%2,%3};"
        : "+f"(c[0]), "+f"(c[1]), "+f"(c[2]), "+f"(c[3])
        : "r"(a[0]), "r"(a[1]), "r"(a[2]), "r"(a[3]), "r"(b0), "r"(b1));
}

__device__ __forceinline__ uint32_t pack2(__nv_bfloat16 lo, __nv_bfloat16 hi) {
    return (uint32_t)__bfloat16_as_ushort(lo) |
           ((uint32_t)__bfloat16_as_ushort(hi) << 16);
}
__device__ __forceinline__ void split_bf16(float v, __nv_bfloat16& h, __nv_bfloat16& l) {
    h = __float2bfloat16(v);
    l = __float2bfloat16(v - __bfloat162float(h));
}

// ---------------- prepass: A [b][m][k] -> swizzled hi/lo tiles ----------------
__global__ void __launch_bounds__(THREADS)
conv_a_kernel(const float* __restrict__ A) {
    const int f = blockIdx.x * THREADS + threadIdx.x;   // float4 id
    const int rg = f >> 4;          // global row (b*1024 + m)
    const int q  = f & 15;          // k quad
    float4 v = *reinterpret_cast<const float4*>(A + (size_t)rg * K_DIM + q * 4);
    __nv_bfloat16 hx, lx, hy, ly, hz, lz, hw, lw;
    split_bf16(v.x, hx, lx); split_bf16(v.y, hy, ly);
    split_bf16(v.z, hz, lz); split_bf16(v.w, hw, lw);
    uint2 hi = make_uint2(pack2(hx, hy), pack2(hz, hw));
    uint2 lo = make_uint2(pack2(lx, ly), pack2(lz, lw));
    const int tile = rg >> 7;                           // b*8 + m/128
    const uint32_t off = (uint32_t)tile * TILE_BYTES +
                         SW128((uint32_t)((rg & 127) * 128 + q * 8));
    *reinterpret_cast<uint2*>((char*)gA0 + off) = hi;
    *reinterpret_cast<uint2*>((char*)gA1 + off) = lo;
}

// ---------------- prepass: B [b][k][n] -> transposed swizzled hi/lo tiles ----
__global__ void __launch_bounds__(THREADS)
conv_b_kernel(const float* __restrict__ B) {
    const int c = blockIdx.x * THREADS + threadIdx.x;   // column id (b*1024+n)
    const int b = c >> 10;
    const int n = c & 1023;
    const float* col = B + (size_t)b * K_DIM * N_DIM + n;
    const int tile = b * 8 + (n >> 7);
    const uint32_t rowbase = (uint32_t)((n & 127) * 128);
#pragma unroll
    for (int k8 = 0; k8 < 8; k8++) {
        float v[8];
#pragma unroll
        for (int j = 0; j < 8; j++) v[j] = col[(size_t)(k8 * 8 + j) * N_DIM];
        __nv_bfloat16 h[8], l[8];
#pragma unroll
        for (int j = 0; j < 8; j++) split_bf16(v[j], h[j], l[j]);
        uint4 hi, lo;
        hi.x = pack2(h[0], h[1]); hi.y = pack2(h[2], h[3]);
        hi.z = pack2(h[4], h[5]); hi.w = pack2(h[6], h[7]);
        lo.x = pack2(l[0], l[1]); lo.y = pack2(l[2], l[3]);
        lo.z = pack2(l[4], l[5]); lo.w = pack2(l[6], l[7]);
        const uint32_t off = (uint32_t)tile * TILE_BYTES +
                             SW128(rowbase + k8 * 16);
        *reinterpret_cast<uint4*>((char*)gB0 + off) = hi;
        *reinterpret_cast<uint4*>((char*)gB1 + off) = lo;
    }
}

// ---------------- GEMM ----------------
__global__ void __launch_bounds__(THREADS, 2)
bmm_hmma_kernel(float* __restrict__ C) {
    extern __shared__ __align__(1024) char smem[];
    const uint32_t smem_base = smem_u32(smem);
    const int tid = threadIdx.x;
    const int wid = tid >> 5;
    const int lid = tid & 31;

    const int bz   = blockIdx.z;
    const int row0 = blockIdx.y * 128;
    const int tileA = bz * 8 + blockIdx.y;
    const int nt0   = blockIdx.x * NT_PER_CTA;
    float* __restrict__ Cb = C + (size_t)bz * M_DIM * N_DIM;

    // ---- prologue: A tiles + first two B stages via cp.async ----
    {
        const char* sa0 = (const char*)gA0 + (size_t)tileA * TILE_BYTES;
        const char* sa1 = (const char*)gA1 + (size_t)tileA * TILE_BYTES;
#pragma unroll
        for (int i = 0; i < 4; i++) {
            const int c = (tid + i * THREADS) * 16;
            cp16(smem_base + SMEM_A0 + c, sa0 + c);
            cp16(smem_base + SMEM_A1 + c, sa1 + c);
        }
        // B stage 0 (tile nt0+0)
        const size_t tb0 = (size_t)(bz * 8 + nt0) * TILE_BYTES;
#pragma unroll
        for (int i = 0; i < 4; i++) {
            const int c = (tid + i * THREADS) * 16;
            cp16(smem_base + SMEM_BS(0) + c,         (const char*)gB0 + tb0 + c);
            cp16(smem_base + SMEM_BS(0) + 16384 + c, (const char*)gB1 + tb0 + c);
        }
        CP_COMMIT();   // group 0: A + B stage0
        // B stage 1 (tile nt0+1)
        const size_t tb1 = (size_t)(bz * 8 + nt0 + 1) * TILE_BYTES;
#pragma unroll
        for (int i = 0; i < 4; i++) {
            const int c = (tid + i * THREADS) * 16;
            cp16(smem_base + SMEM_BS(1) + c,         (const char*)gB0 + tb1 + c);
            cp16(smem_base + SMEM_BS(1) + 16384 + c, (const char*)gB1 + tb1 + c);
        }
        CP_COMMIT();   // group 1: B stage1
    }

    // ---- warp tiling: warp_m = wid%4 (32 rows), warp_n = wid/4 (64 cols) ----
    const int warp_m = wid & 3;
    const int warp_n = wid >> 2;
    const int g = lid >> 3;
    const int r8 = lid & 7;
    const int a_row_l = warp_m * 32 + (g & 1) * 8 + r8;
    const int a_kb_l  = (g >> 1) * 16;
    const int b_row_l = warp_n * 64 + (g >> 1) * 8 + r8;
    const int b_kb_l  = (g & 1) * 16;
    const int tq = lid & 3;
    const int tr = lid >> 2;

#pragma unroll
    for (int t = 0; t < NT_PER_CTA; t++) {
        if (t < NT_PER_CTA - 1)
            asm volatile("cp.async.wait_group 1;" ::: "memory");
        else
            asm volatile("cp.async.wait_group 0;" ::: "memory");
        __syncthreads();

        const uint32_t bst = smem_base + SMEM_BS(t & 1);

        float acc[2][8][4];
#pragma unroll
        for (int mi = 0; mi < 2; mi++)
#pragma unroll
            for (int ni = 0; ni < 8; ni++)
#pragma unroll
                for (int j = 0; j < 4; j++) acc[mi][ni][j] = 0.0f;

#pragma unroll
        for (int ks = 0; ks < 4; ks++) {
            const uint32_t a_off  = SW128((uint32_t)(a_row_l * 128 + ks * 32 + a_kb_l));
            const uint32_t a_off2 = SW128((uint32_t)((a_row_l + 16) * 128 + ks * 32 + a_kb_l));

            uint32_t b0f[8][2];
#pragma unroll
            for (int nq = 0; nq < 4; nq++) {
                uint32_t rr[4];
                ldsm_x4(rr, bst + SW128((uint32_t)((b_row_l + nq * 16) * 128 + ks * 32 + b_kb_l)));
                b0f[nq * 2 + 0][0] = rr[0]; b0f[nq * 2 + 0][1] = rr[1];
                b0f[nq * 2 + 1][0] = rr[2]; b0f[nq * 2 + 1][1] = rr[3];
            }
            uint32_t a0f[2][4];
            ldsm_x4(a0f[0], smem_base + SMEM_A0 + a_off);
            ldsm_x4(a0f[1], smem_base + SMEM_A0 + a_off2);
            uint32_t a1f[2][4];
            ldsm_x4(a1f[0], smem_base + SMEM_A1 + a_off);
            ldsm_x4(a1f[1], smem_base + SMEM_A1 + a_off2);

#pragma unroll
            for (int mi = 0; mi < 2; mi++)
#pragma unroll
                for (int ni = 0; ni < 8; ni++)
                    mma_bf16(acc[mi][ni], a0f[mi], b0f[ni][0], b0f[ni][1]);
#pragma unroll
            for (int mi = 0; mi < 2; mi++)
#pragma unroll
                for (int ni = 0; ni < 8; ni++)
                    mma_bf16(acc[mi][ni], a1f[mi], b0f[ni][0], b0f[ni][1]);

            uint32_t b1f[8][2];
#pragma unroll
            for (int nq = 0; nq < 4; nq++) {
                uint32_t rr[4];
                ldsm_x4(rr, bst + 16384 +
                            SW128((uint32_t)((b_row_l + nq * 16) * 128 + ks * 32 + b_kb_l)));
                b1f[nq * 2 + 0][0] = rr[0]; b1f[nq * 2 + 0][1] = rr[1];
                b1f[nq * 2 + 1][0] = rr[2]; b1f[nq * 2 + 1][1] = rr[3];
            }
#pragma unroll
            for (int mi = 0; mi < 2; mi++)
#pragma unroll
                for (int ni = 0; ni < 8; ni++)
                    mma_bf16(acc[mi][ni], a0f[mi], b1f[ni][0], b1f[ni][1]);
        }

        __syncthreads();   // all warps done reading this B stage

        // issue B loads for tile t+2 into the stage we just freed
        if (t + 2 < NT_PER_CTA) {
            const size_t tb = (size_t)(bz * 8 + nt0 + t + 2) * TILE_BYTES;
            const uint32_t dst = smem_base + SMEM_BS(t & 1);
#pragma unroll
            for (int i = 0; i < 4; i++) {
                const int c = (tid + i * THREADS) * 16;
                cp16(dst + c,         (const char*)gB0 + tb + c);
                cp16(dst + 16384 + c, (const char*)gB1 + tb + c);
            }
        }
        CP_COMMIT();   // keep group accounting uniform (empty group ok)

        // ---- epilogue for this n-tile ----
        const int col0 = (nt0 + t) * 128;
#pragma unroll
        for (int mi = 0; mi < 2; mi++) {
            const int rbase = row0 + warp_m * 32 + mi * 16 + tr;
            float* c0 = &Cb[(size_t)rbase * N_DIM + col0 + warp_n * 64 + tq * 2];
            float* c1 = c0 + 8 * N_DIM;
#pragma unroll
            for (int ni = 0; ni < 8; ni++) {
                *reinterpret_cast<float2*>(c0 + ni * 8) =
                    make_float2(acc[mi][ni][0], acc[mi][ni][1]);
                *reinterpret_cast<float2*>(c1 + ni * 8) =
                    make_float2(acc[mi][ni][2], acc[mi][ni][3]);
            }
        }
    }
}

extern "C" void kernel_launch(void* const* d_in, const int* in_sizes, int n_in,
                              void* d_out, int out_size) {
    const float* A = (const float*)d_in[0];   // [2,12,1024,64]
    const float* B = (const float*)d_in[1];   // [2,12,64,1024]
    float* C = (float*)d_out;                 // [2,12,1024,1024]

    conv_a_kernel<<<BATCH * M_DIM * K_DIM / 4 / THREADS, THREADS>>>(A);  // 1536 blocks
    conv_b_kernel<<<BATCH * N_DIM / THREADS, THREADS>>>(B);              // 96 blocks

    cudaFuncSetAttribute(bmm_hmma_kernel,
                         cudaFuncAttributeMaxDynamicSharedMemorySize, SMEM_TOTAL);
    dim3 grid(N_DIM / 128 / NT_PER_CTA, M_DIM / 128, BATCH);  // (2, 8, 24)
    bmm_hmma_kernel<<<grid, THREADS, SMEM_TOTAL>>>(C);
}

// round 6
// speedup vs baseline: 1.3035x; 1.3035x over previous
#include <cuda_runtime.h>
#include <cstdint>

// C[b] = A[b](1024x64) @ B[b](64x1024), fp32, b in [0,24).
// Single-pass TF32 mma.sync (m16n8k8). Smem holds A/B tf32 in fragment-order
// layout (XOR-swizzled) so compute uses plain LDS.128/LDS.64 (no ldmatrix).
// CTA tile 128x128, full K=64 resident. 256 threads = 8 warps, warp 32x64.

#define M_DIM 1024
#define N_DIM 1024
#define K_DIM 64
#define BATCH 24
#define THREADS 256

// smem: A frags 8mf*8kf*32lane*16B = 32KB ; B frags 16nf*8kf*32lane*8B = 32KB
#define SMEM_A 0
#define SMEM_B 32768
#define SMEM_TOTAL 65536

__device__ __forceinline__ uint32_t cvt_tf32(float v) {
    uint32_t u;
    asm("cvt.rna.tf32.f32 %0, %1;" : "=r"(u) : "f"(v));
    return u;
}

__device__ __forceinline__ void mma_tf32(float* c, const uint32_t* a,
                                         uint32_t b0, uint32_t b1) {
    asm volatile(
        "mma.sync.aligned.m16n8k8.row.col.f32.tf32.tf32.f32 "
        "{%0,%1,%2,%3}, {%4,%5,%6,%7}, {%8,%9}, {%0,%1,%2,%3};"
        : "+f"(c[0]), "+f"(c[1]), "+f"(c[2]), "+f"(c[3])
        : "r"(a[0]), "r"(a[1]), "r"(a[2]), "r"(a[3]), "r"(b0), "r"(b1));
}

__global__ void __launch_bounds__(THREADS, 2)
bmm_tf32_kernel(const float* __restrict__ A,
                const float* __restrict__ B,
                float* __restrict__ C) {
    extern __shared__ __align__(1024) char smem[];
    uint32_t* sA = reinterpret_cast<uint32_t*>(smem + SMEM_A);
    uint32_t* sB = reinterpret_cast<uint32_t*>(smem + SMEM_B);

    const int tid = threadIdx.x;
    const int wid = tid >> 5;
    const int lid = tid & 31;

    const int bz   = blockIdx.z;
    const int row0 = blockIdx.y * 128;
    const int col0 = blockIdx.x * 128;

    const float* __restrict__ Ab = A + (size_t)bz * M_DIM * K_DIM;
    const float* __restrict__ Bb = B + (size_t)bz * K_DIM * N_DIM;
    float*       __restrict__ Cb = C + (size_t)bz * M_DIM * N_DIM;

    // ---- A tile: [128 m][64 k] fp32 -> tf32 fragment-order smem ----
    // frag (mf=m/16, kf=k/8): element (r=m%16, c=k%8):
    //   lane = (r%8)*4 + (c%4), reg = r/8 + 2*(c/4)
    //   granule = lane ^ kf  (XOR spreads store banks across kf)
    //   word addr = (frag*32 + granule)*4 + reg
#pragma unroll
    for (int i = 0; i < 8; i++) {
        const int f = tid + i * THREADS;    // float4 id, 0..2047
        const int m = f >> 4;
        const int q = f & 15;               // k quad: k = 4q..4q+3
        float4 v = *reinterpret_cast<const float4*>(
            &Ab[(size_t)(row0 + m) * K_DIM + q * 4]);
        const int kf   = q >> 1;
        const int frag = (m >> 4) * 8 + kf;
        const int reg  = ((m & 15) >> 3) + 2 * (q & 1);
        const int lw   = (m & 7) * 4;       // lane base (j added per scalar)
        uint32_t t[4] = {cvt_tf32(v.x), cvt_tf32(v.y), cvt_tf32(v.z), cvt_tf32(v.w)};
#pragma unroll
        for (int j = 0; j < 4; j++) {
            const int granule = (lw + j) ^ kf;
            sA[(frag * 32 + granule) * 4 + reg] = t[j];
        }
    }

    // ---- B tile: global [64 k][128 n] -> tf32 fragment-order smem ----
    // frag (nf=n/8, kf=k/8): element (k,n): lane=(n%8)*4+(k%4), reg=(k%8)/4
    //   granule = lane ^ (nf&3); 8B granule holds (reg0, reg1) -> STS.64
    {
        const int n  = tid & 127;
        const int kh = (tid >> 7) * 32;
        const int nf = n >> 3;
        const float* bcol = Bb + col0 + n;
#pragma unroll
        for (int kg = 0; kg < 4; kg++) {
            const int kbase = kh + kg * 8;
            const int kf    = kbase >> 3;
            const int frag  = nf * 8 + kf;
            float v[8];
#pragma unroll
            for (int j = 0; j < 8; j++)
                v[j] = bcol[(size_t)(kbase + j) * N_DIM];
#pragma unroll
            for (int j = 0; j < 4; j++) {
                const int granule = (((n & 7) * 4 + j) ^ (nf & 3));
                uint2 w = make_uint2(cvt_tf32(v[j]), cvt_tf32(v[j + 4]));
                *reinterpret_cast<uint2*>(&sB[(frag * 32 + granule) * 2]) = w;
            }
        }
    }

    __syncthreads();

    // ---- warp tiling: warp_m = wid%4 (32 rows), warp_n = wid/4 (64 cols) ----
    const int warp_m = wid & 3;
    const int warp_n = wid >> 2;

    float acc[2][8][4];
#pragma unroll
    for (int mi = 0; mi < 2; mi++)
#pragma unroll
        for (int ni = 0; ni < 8; ni++)
#pragma unroll
            for (int j = 0; j < 4; j++) acc[mi][ni][j] = 0.0f;

#pragma unroll
    for (int kf = 0; kf < 8; kf++) {
        // A fragments: mf = warp_m*2 + {0,1}, LDS.128 each
        uint32_t af[2][4];
#pragma unroll
        for (int mi = 0; mi < 2; mi++) {
            const int frag = (warp_m * 2 + mi) * 8 + kf;
            const int granule = lid ^ kf;
            uint4 r = *reinterpret_cast<const uint4*>(&sA[(frag * 32 + granule) * 4]);
            af[mi][0] = r.x; af[mi][1] = r.y; af[mi][2] = r.z; af[mi][3] = r.w;
        }
        // B fragments: nf = warp_n*8 + 0..7, LDS.64 each
        uint32_t bf[8][2];
#pragma unroll
        for (int ni = 0; ni < 8; ni++) {
            const int nf = warp_n * 8 + ni;
            const int frag = nf * 8 + kf;
            const int granule = lid ^ (nf & 3);
            uint2 r = *reinterpret_cast<const uint2*>(&sB[(frag * 32 + granule) * 2]);
            bf[ni][0] = r.x; bf[ni][1] = r.y;
        }
#pragma unroll
        for (int mi = 0; mi < 2; mi++)
#pragma unroll
            for (int ni = 0; ni < 8; ni++)
                mma_tf32(acc[mi][ni], af[mi], bf[ni][0], bf[ni][1]);
    }

    // ---- epilogue: direct float2 stores (same C frag layout as m16n8k16) ----
    const int tq = lid & 3;
    const int tr = lid >> 2;
#pragma unroll
    for (int mi = 0; mi < 2; mi++) {
        const int rbase = row0 + warp_m * 32 + mi * 16 + tr;
        float* c0 = &Cb[(size_t)rbase * N_DIM + col0 + warp_n * 64 + tq * 2];
        float* c1 = c0 + 8 * N_DIM;
#pragma unroll
        for (int ni = 0; ni < 8; ni++) {
            *reinterpret_cast<float2*>(c0 + ni * 8) =
                make_float2(acc[mi][ni][0], acc[mi][ni][1]);
            *reinterpret_cast<float2*>(c1 + ni * 8) =
                make_float2(acc[mi][ni][2], acc[mi][ni][3]);
        }
    }
}

extern "C" void kernel_launch(void* const* d_in, const int* in_sizes, int n_in,
                              void* d_out, int out_size) {
    const float* A = (const float*)d_in[0];   // [2,12,1024,64]
    const float* B = (const float*)d_in[1];   // [2,12,64,1024]
    float* C = (float*)d_out;                 // [2,12,1024,1024]

    cudaFuncSetAttribute(bmm_tf32_kernel,
                         cudaFuncAttributeMaxDynamicSharedMemorySize, SMEM_TOTAL);
    dim3 grid(N_DIM / 128, M_DIM / 128, BATCH);  // (8, 8, 24)
    bmm_tf32_kernel<<<grid, THREADS, SMEM_TOTAL>>>(A, B, C);
}

// round 7
// speedup vs baseline: 1.5425x; 1.1834x over previous
#include <cuda_runtime.h>
#include <cuda_fp16.h>
#include <cstdint>

// C[b] = A[b](1024x64) @ B[b](64x1024), fp32, b in [0,24).
// Single-pass fp16 mma.sync (m16n8k16, fp32 accum). fp16 mantissa == tf32
// mantissa (11 bits) so accuracy matches tf32 (~3e-4) at half the smem bytes.
// CTA tile 128x128, full K=64 resident. 256 threads = 8 warps, warp 32x64.

#define M_DIM 1024
#define N_DIM 1024
#define K_DIM 64
#define BATCH 24
#define THREADS 256

// smem: A tile 128x64 fp16 (128B rows, SW128) + B tile transposed 128x64 fp16
#define SMEM_A 0
#define SMEM_B 16384
#define SMEM_TOTAL 32768

#define SW128(o) ((o) ^ (((o) >> 3) & 0x70))

__device__ __forceinline__ uint32_t smem_u32(const void* p) {
    uint32_t a;
    asm("{ .reg .u64 t; cvta.to.shared.u64 t, %1; cvt.u32.u64 %0, t; }"
        : "=r"(a) : "l"(p));
    return a;
}

__device__ __forceinline__ void ldsm_x4(uint32_t* r, uint32_t addr) {
    asm volatile("ldmatrix.sync.aligned.m8n8.x4.shared.b16 {%0,%1,%2,%3}, [%4];"
                 : "=r"(r[0]), "=r"(r[1]), "=r"(r[2]), "=r"(r[3])
                 : "r"(addr));
}

__device__ __forceinline__ void mma_fp16(float* c, const uint32_t* a,
                                         uint32_t b0, uint32_t b1) {
    asm volatile(
        "mma.sync.aligned.m16n8k16.row.col.f32.f16.f16.f32 "
        "{%0,%1,%2,%3}, {%4,%5,%6,%7}, {%8,%9}, {%0,%1,%2,%3};"
        : "+f"(c[0]), "+f"(c[1]), "+f"(c[2]), "+f"(c[3])
        : "r"(a[0]), "r"(a[1]), "r"(a[2]), "r"(a[3]), "r"(b0), "r"(b1));
}

__device__ __forceinline__ uint32_t packh2(float a, float b) {
    uint32_t r;
    asm("{ .reg .f16 lo, hi;\n\t"
        "  cvt.rn.f16.f32 lo, %1;\n\t"
        "  cvt.rn.f16.f32 hi, %2;\n\t"
        "  mov.b32 %0, {lo, hi}; }"
        : "=r"(r) : "f"(a), "f"(b));
    return r;
}

__global__ void __launch_bounds__(THREADS, 2)
bmm_fp16_kernel(const float* __restrict__ A,
                const float* __restrict__ B,
                float* __restrict__ C) {
    extern __shared__ __align__(1024) char smem[];
    const uint32_t smem_base = smem_u32(smem);
    const int tid = threadIdx.x;
    const int wid = tid >> 5;
    const int lid = tid & 31;

    const int bz   = blockIdx.z;
    const int row0 = blockIdx.y * 128;
    const int col0 = blockIdx.x * 128;

    const float* __restrict__ Ab = A + (size_t)bz * M_DIM * K_DIM;
    const float* __restrict__ Bb = B + (size_t)bz * K_DIM * N_DIM;
    float*       __restrict__ Cb = C + (size_t)bz * M_DIM * N_DIM;

    // ---- A tile: [128 m][64 k] fp32 -> fp16 smem (row-major 128B rows, SW128) ----
#pragma unroll
    for (int i = 0; i < 8; i++) {
        const int f = tid + i * THREADS;    // float4 id
        const int r = f >> 4;
        const int q = f & 15;               // k quad
        float4 v = *reinterpret_cast<const float4*>(
            &Ab[(size_t)(row0 + r) * K_DIM + q * 4]);
        uint2 h = make_uint2(packh2(v.x, v.y), packh2(v.z, v.w));
        const uint32_t off = SW128((uint32_t)(r * 128 + q * 8));
        *reinterpret_cast<uint2*>(smem + SMEM_A + off) = h;
    }

    // ---- B tile: global [64 k][128 n] -> smem BT[n][k] fp16 (SW128) ----
    {
        const int n  = tid & 127;
        const int kh = (tid >> 7) * 32;
        const float* bcol = Bb + col0 + n;
#pragma unroll
        for (int k8 = 0; k8 < 4; k8++) {
            float v[8];
#pragma unroll
            for (int j = 0; j < 8; j++)
                v[j] = bcol[(size_t)(kh + k8 * 8 + j) * N_DIM];
            uint4 h;
            h.x = packh2(v[0], v[1]); h.y = packh2(v[2], v[3]);
            h.z = packh2(v[4], v[5]); h.w = packh2(v[6], v[7]);
            const uint32_t off = SW128((uint32_t)(n * 128 + (kh + k8 * 8) * 2));
            *reinterpret_cast<uint4*>(smem + SMEM_B + off) = h;
        }
    }

    __syncthreads();

    // ---- warp tiling: warp_m = wid%4 (32 rows), warp_n = wid/4 (64 cols) ----
    const int warp_m = wid & 3;
    const int warp_n = wid >> 2;
    const int g = lid >> 3;
    const int r8 = lid & 7;
    const int a_row_l = warp_m * 32 + (g & 1) * 8 + r8;
    const int a_kb_l  = (g >> 1) * 16;
    const int b_row_l = warp_n * 64 + (g >> 1) * 8 + r8;
    const int b_kb_l  = (g & 1) * 16;

    float acc[2][8][4];
#pragma unroll
    for (int mi = 0; mi < 2; mi++)
#pragma unroll
        for (int ni = 0; ni < 8; ni++)
#pragma unroll
            for (int j = 0; j < 4; j++) acc[mi][ni][j] = 0.0f;

#pragma unroll
    for (int ks = 0; ks < 4; ks++) {
        uint32_t af[2][4];
        ldsm_x4(af[0], smem_base + SMEM_A +
                       SW128((uint32_t)(a_row_l * 128 + ks * 32 + a_kb_l)));
        ldsm_x4(af[1], smem_base + SMEM_A +
                       SW128((uint32_t)((a_row_l + 16) * 128 + ks * 32 + a_kb_l)));
        uint32_t bf[8][2];
#pragma unroll
        for (int nq = 0; nq < 4; nq++) {
            uint32_t rr[4];
            ldsm_x4(rr, smem_base + SMEM_B +
                        SW128((uint32_t)((b_row_l + nq * 16) * 128 + ks * 32 + b_kb_l)));
            bf[nq * 2 + 0][0] = rr[0]; bf[nq * 2 + 0][1] = rr[1];
            bf[nq * 2 + 1][0] = rr[2]; bf[nq * 2 + 1][1] = rr[3];
        }
#pragma unroll
        for (int mi = 0; mi < 2; mi++)
#pragma unroll
            for (int ni = 0; ni < 8; ni++)
                mma_fp16(acc[mi][ni], af[mi], bf[ni][0], bf[ni][1]);
    }

    // ---- epilogue: direct float2 stores ----
    const int tq = lid & 3;
    const int tr = lid >> 2;
#pragma unroll
    for (int mi = 0; mi < 2; mi++) {
        const int rbase = row0 + warp_m * 32 + mi * 16 + tr;
        float* c0 = &Cb[(size_t)rbase * N_DIM + col0 + warp_n * 64 + tq * 2];
        float* c1 = c0 + 8 * N_DIM;
#pragma unroll
        for (int ni = 0; ni < 8; ni++) {
            *reinterpret_cast<float2*>(c0 + ni * 8) =
                make_float2(acc[mi][ni][0], acc[mi][ni][1]);
            *reinterpret_cast<float2*>(c1 + ni * 8) =
                make_float2(acc[mi][ni][2], acc[mi][ni][3]);
        }
    }
}

extern "C" void kernel_launch(void* const* d_in, const int* in_sizes, int n_in,
                              void* d_out, int out_size) {
    const float* A = (const float*)d_in[0];   // [2,12,1024,64]
    const float* B = (const float*)d_in[1];   // [2,12,64,1024]
    float* C = (float*)d_out;                 // [2,12,1024,1024]

    cudaFuncSetAttribute(bmm_fp16_kernel,
                         cudaFuncAttributeMaxDynamicSharedMemorySize, SMEM_TOTAL);
    dim3 grid(N_DIM / 128, M_DIM / 128, BATCH);  // (8, 8, 24)
    bmm_fp16_kernel<<<grid, THREADS, SMEM_TOTAL>>>(A, B, C);
}